// round 5
// baseline (speedup 1.0000x reference)
#include <cuda_runtime.h>
#include <math_constants.h>
#include <cstdint>

#define SS      128
#define BB      64
#define HH      512
#define VV      100
#define TSTEPS  31      // T-1 decode steps
#define G3H     1536
#define NTH     256
#define NB      296     // 2 CTAs per SM on 148 SMs, single wave

// ---------------- persistent scratch ----------------
__device__ float g_hT[2][HH * BB];      // hidden, transposed [h][b]
__device__ float g_ctxT[HH * BB];       // context, transposed
__device__ float g_xp[2][HH * BB];      // comb partial sums [j][b] (0=emb,1=ctx)
__device__ float g_gh[G3H * BB];        // h @ W_hh^T + b_hh   [j][b]
__device__ float g_gi[G3H * BB];        // x @ W_ih^T + b_ih   [j][b]
__device__ float g_lg[VV * BB];         // raw logits [v][b]
__device__ unsigned g_barcnt = 0;
__device__ unsigned g_bargen = 0;

union SmemU {
    struct { float W[32][17]; float A[32][64]; } g;
    struct { float h[HH]; float w[HH]; float sc[SS]; } a;
};

__device__ __forceinline__ float warp_sum(float v) {
#pragma unroll
    for (int o = 16; o; o >>= 1) v += __shfl_xor_sync(0xffffffffu, v, o);
    return v;
}
__device__ __forceinline__ float warp_max(float v) {
#pragma unroll
    for (int o = 16; o; o >>= 1) v = fmaxf(v, __shfl_xor_sync(0xffffffffu, v, o));
    return v;
}
__device__ __forceinline__ float fast_tanh(float x) {
    float r;
    asm("tanh.approx.f32 %0, %1;" : "=f"(r) : "f"(x));
    return r;
}

// Sense-reversing grid barrier (all CTAs resident: 296 = 148 SMs x 2).
__device__ __forceinline__ void gridbar() {
    __syncthreads();
    if (threadIdx.x == 0) {
        __threadfence();
        unsigned gen = *((volatile unsigned*)&g_bargen);
        unsigned old = atomicAdd(&g_barcnt, 1u);
        if (old == NB - 1) {
            atomicExch(&g_barcnt, 0u);
            atomicExch(&g_bargen, gen + 1u);
        } else {
            while (*((volatile unsigned*)&g_bargen) == gen) { __nanosleep(64); }
        }
        __threadfence();
    }
    __syncthreads();
}

// ---------------------------------------------------------------------------
// Tiled GEMM: C[j0..j0+15][0..63] = W[j][k] * A[k][b], K = 512, Kc = 32.
// mode 0: A from transposed activation array A0 ([512][64], cross-block -> ldcg)
// mode 1: A[k][b] = W_emb[syms[b]][k]  (read-only input, plain loads)
// mode 2: A[k][b] = relu(A0[k][b] + A1[k][b] + xbias[k])   (cross-block -> ldcg)
// biasC: optional per-row bias added at epilogue. rowlim guards ragged M.
// ---------------------------------------------------------------------------
__device__ void gemm_tile(SmemU* sm,
                          const float* __restrict__ W, int ldw, int j0, int rowlim,
                          int mode, const float* __restrict__ A0,
                          const float* __restrict__ A1,
                          const float* __restrict__ xbias,
                          const int* __restrict__ syms,
                          const float* __restrict__ biasC,
                          float* __restrict__ Cout)
{
    const int tid = threadIdx.x;
    const int tx = tid & 15;      // j within tile (compute)
    const int ty = tid >> 4;      // b-group (compute), b0 = ty*4
    float acc0 = 0.f, acc1 = 0.f, acc2 = 0.f, acc3 = 0.f;

    for (int kc = 0; kc < HH; kc += 32) {
        // ---- load W tile (16 rows x 32 k) ----
        {
            int j = tid >> 4;                 // 0..15
            int kk = (tid & 15) * 2;          // 0..30
            int row = j0 + j;
            int r = row < rowlim ? row : rowlim - 1;
            const float2 w2 = *(const float2*)(W + (size_t)r * ldw + kc + kk);
            sm->g.W[kk][j]     = w2.x;
            sm->g.W[kk + 1][j] = w2.y;
        }
        // ---- load A tile (32 k x 64 b) ----
        if (mode == 0) {
            const float4* src = (const float4*)(A0 + (size_t)kc * BB);
            float4* dst = (float4*)&sm->g.A[0][0];
            dst[tid]       = __ldcg(&src[tid]);
            dst[tid + 256] = __ldcg(&src[tid + 256]);
        } else if (mode == 1) {
            int b = tid >> 2;
            int kg = (tid & 3) * 8;
            const float* src = A0 + (size_t)syms[b] * HH + kc + kg;
            float4 v0 = *(const float4*)src;
            float4 v1 = *(const float4*)(src + 4);
            sm->g.A[kg + 0][b] = v0.x; sm->g.A[kg + 1][b] = v0.y;
            sm->g.A[kg + 2][b] = v0.z; sm->g.A[kg + 3][b] = v0.w;
            sm->g.A[kg + 4][b] = v1.x; sm->g.A[kg + 5][b] = v1.y;
            sm->g.A[kg + 6][b] = v1.z; sm->g.A[kg + 7][b] = v1.w;
        } else {
            int e = tid * 8;                  // 8 consecutive (k*64+b), same k
            int k = e >> 6;
            float bv = xbias[kc + k];
            float4 u0 = __ldcg((const float4*)(A0 + (size_t)kc * BB + e));
            float4 u1 = __ldcg((const float4*)(A0 + (size_t)kc * BB + e + 4));
            float4 v0 = __ldcg((const float4*)(A1 + (size_t)kc * BB + e));
            float4 v1 = __ldcg((const float4*)(A1 + (size_t)kc * BB + e + 4));
            float* dst = &sm->g.A[0][0] + e;
            dst[0] = fmaxf(u0.x + v0.x + bv, 0.f);
            dst[1] = fmaxf(u0.y + v0.y + bv, 0.f);
            dst[2] = fmaxf(u0.z + v0.z + bv, 0.f);
            dst[3] = fmaxf(u0.w + v0.w + bv, 0.f);
            dst[4] = fmaxf(u1.x + v1.x + bv, 0.f);
            dst[5] = fmaxf(u1.y + v1.y + bv, 0.f);
            dst[6] = fmaxf(u1.z + v1.z + bv, 0.f);
            dst[7] = fmaxf(u1.w + v1.w + bv, 0.f);
        }
        __syncthreads();
#pragma unroll
        for (int k = 0; k < 32; k++) {
            float w = sm->g.W[k][tx];
            float4 a = *(const float4*)&sm->g.A[k][ty << 2];
            acc0 = fmaf(w, a.x, acc0);
            acc1 = fmaf(w, a.y, acc1);
            acc2 = fmaf(w, a.z, acc2);
            acc3 = fmaf(w, a.w, acc3);
        }
        __syncthreads();
    }
    int row = j0 + tx;
    if (row < rowlim) {
        float bb = biasC ? biasC[row] : 0.f;
        float4 r4 = make_float4(acc0 + bb, acc1 + bb, acc2 + bb, acc3 + bb);
        *(float4*)(Cout + (size_t)row * BB + (ty << 2)) = r4;
    }
}

// ---------------------------------------------------------------------------
// Bahdanau attention for batch element b (block-collective).
// ---------------------------------------------------------------------------
__device__ void attention_block(SmemU* sm, int b,
                                const float* __restrict__ enc,
                                const float* __restrict__ w_vat,
                                const float* __restrict__ b_vat,
                                const float* __restrict__ hT,
                                float* __restrict__ ctxT)
{
    const int tid = threadIdx.x, wid = tid >> 5, lane = tid & 31;
    for (int i = tid; i < HH; i += NTH) {
        sm->a.h[i] = __ldcg(&hT[i * BB + b]);
        sm->a.w[i] = w_vat[i];
    }
    __syncthreads();
    const float bv = b_vat[0];
    const float4* hp = (const float4*)sm->a.h;
    const float4* wp = (const float4*)sm->a.w;
    for (int s = wid; s < SS; s += NTH / 32) {
        const float4* ep = (const float4*)(enc + ((size_t)s * BB + b) * HH);
        float acc = 0.f;
#pragma unroll
        for (int c = 0; c < 4; c++) {
            int k = lane + 32 * c;
            float4 e = ep[k], h4 = hp[k], w4 = wp[k];
            acc += fast_tanh(e.x + h4.x) * w4.x;
            acc += fast_tanh(e.y + h4.y) * w4.y;
            acc += fast_tanh(e.z + h4.z) * w4.z;
            acc += fast_tanh(e.w + h4.w) * w4.w;
        }
        acc = warp_sum(acc);
        if (lane == 0) sm->a.sc[s] = acc + bv;
    }
    __syncthreads();
    if (wid == 0) {
        float v0 = sm->a.sc[lane],      v1 = sm->a.sc[lane + 32];
        float v2 = sm->a.sc[lane + 64], v3 = sm->a.sc[lane + 96];
        float m = warp_max(fmaxf(fmaxf(v0, v1), fmaxf(v2, v3)));
        float e0 = expf(v0 - m), e1 = expf(v1 - m);
        float e2 = expf(v2 - m), e3 = expf(v3 - m);
        float inv = 1.f / warp_sum(e0 + e1 + e2 + e3);
        sm->a.sc[lane]      = e0 * inv; sm->a.sc[lane + 32] = e1 * inv;
        sm->a.sc[lane + 64] = e2 * inv; sm->a.sc[lane + 96] = e3 * inv;
    }
    __syncthreads();
    {
        const int h0 = tid * 2;
        const float* base = enc + (size_t)b * HH + h0;
        float a0 = 0.f, a1 = 0.f;
#pragma unroll 4
        for (int s = 0; s < SS; s++) {
            float wv = sm->a.sc[s];
            float2 e = *(const float2*)(base + (size_t)s * (BB * HH));
            a0 = fmaf(wv, e.x, a0);
            a1 = fmaf(wv, e.y, a1);
        }
        ctxT[h0 * BB + b]       = a0;
        ctxT[(h0 + 1) * BB + b] = a1;
    }
    __syncthreads();
}

// log-softmax of one raw-logit column b (one warp), write to out slot.
__device__ void lsm_row(int b, float* __restrict__ outp)
{
    const int lane = threadIdx.x & 31;
    float v0 = __ldcg(&g_lg[lane * BB + b]);
    float v1 = __ldcg(&g_lg[(lane + 32) * BB + b]);
    float v2 = __ldcg(&g_lg[(lane + 64) * BB + b]);
    bool ok3 = lane < (VV - 96);
    float v3 = ok3 ? __ldcg(&g_lg[(lane + 96) * BB + b]) : -CUDART_INF_F;
    float m = warp_max(fmaxf(fmaxf(v0, v1), fmaxf(v2, v3)));
    float s = expf(v0 - m) + expf(v1 - m) + expf(v2 - m) + (ok3 ? expf(v3 - m) : 0.f);
    s = warp_sum(s);
    float lse = m + logf(s);
    outp[lane]      = v0 - lse;
    outp[lane + 32] = v1 - lse;
    outp[lane + 64] = v2 - lse;
    if (ok3) outp[lane + 96] = v3 - lse;
}

__global__ void __launch_bounds__(NTH, 2)
bahdanau_kernel(
    const float* __restrict__ enc,    const float* __restrict__ W_emb,
    const float* __restrict__ W_comb, const float* __restrict__ b_comb,
    const float* __restrict__ W_ih,   const float* __restrict__ W_hh,
    const float* __restrict__ b_ih,   const float* __restrict__ b_hh,
    const float* __restrict__ W_out,  const float* __restrict__ b_out,
    const float* __restrict__ w_vat,  const float* __restrict__ b_vat,
    const int* __restrict__ tgt, float* __restrict__ out)
{
    const int bid = blockIdx.x;
    const int tid = threadIdx.x;
    const int wid = tid >> 5;
    __shared__ SmemU sm;

    // zero initial hidden state
    for (int i = bid * NTH + tid; i < HH * BB; i += NB * NTH) g_hT[0][i] = 0.f;
    gridbar();

    for (int t = 0; t < TSTEPS; t++) {
        const float* hcur = g_hT[t & 1];
        float* hnext = g_hT[(t + 1) & 1];

        // === Phase A: attention(64) | gh all 96 tiles | logits prev (7)
        //              | comb-emb (32, independent of ctx) ===
        if (bid < BB) {
            attention_block(&sm, bid, enc, w_vat, b_vat, hcur, g_ctxT);
        } else if (bid < 160) {
            int j0 = (bid - 64) * 16;                        // 0..1520
            gemm_tile(&sm, W_hh, HH, j0, G3H, 0, hcur, nullptr, nullptr,
                      nullptr, b_hh, g_gh);
        } else if (bid < 167) {
            if (t >= 1) {
                int j0 = (bid - 160) * 16;                   // 0..96
                gemm_tile(&sm, W_out, HH, j0, VV, 0, hcur, nullptr, nullptr,
                          nullptr, b_out, g_lg);
            }
        } else if (bid < 199) {
            int j0 = (bid - 167) * 16;                       // 0..496
            gemm_tile(&sm, W_comb, 2 * HH, j0, HH, 1, W_emb, nullptr,
                      nullptr, tgt + t * BB, nullptr, g_xp[0]);
        }
        gridbar();

        // === Phase B: comb-ctx (32) | log-softmax prev (8) ===
        if (bid < 32) {
            int j0 = bid * 16;
            gemm_tile(&sm, W_comb + HH, 2 * HH, j0, HH, 0, g_ctxT, nullptr,
                      nullptr, nullptr, nullptr, g_xp[1]);
        } else if (bid < 40) {
            if (t >= 1) {
                int b = (bid - 32) * 8 + wid;
                lsm_row(b, out + (size_t)b * TSTEPS * VV + (size_t)(t - 1) * VV);
            }
        }
        gridbar();

        // === Phase C: gi tiles (x materialized in A-loader) ===
        if (bid < 96) {
            int j0 = bid * 16;
            gemm_tile(&sm, W_ih, HH, j0, G3H, 2, g_xp[0], g_xp[1], b_comb,
                      nullptr, b_ih, g_gi);
        }
        gridbar();

        // === Phase D: GRU gates elementwise ===
        {
            int e = bid * NTH + tid;
            if (e < HH * BB) {
                int i = e >> 6, b = e & 63;
                float gir = __ldcg(&g_gi[i * BB + b]);
                float giz = __ldcg(&g_gi[(i + HH) * BB + b]);
                float gin = __ldcg(&g_gi[(i + 2 * HH) * BB + b]);
                float ghr = __ldcg(&g_gh[i * BB + b]);
                float ghz = __ldcg(&g_gh[(i + HH) * BB + b]);
                float ghn = __ldcg(&g_gh[(i + 2 * HH) * BB + b]);
                float ho  = __ldcg(&hcur[i * BB + b]);
                float r = 1.f / (1.f + expf(-(gir + ghr)));
                float z = 1.f / (1.f + expf(-(giz + ghz)));
                float n = tanhf(gin + r * ghn);
                hnext[i * BB + b] = (1.f - z) * n + z * ho;
            }
        }
        gridbar();
    }

    // ===== final logits: slot TSTEPS-1 from final h =====
    const float* hfin = g_hT[TSTEPS & 1];
    if (bid < 7) {
        int j0 = bid * 16;
        gemm_tile(&sm, W_out, HH, j0, VV, 0, hfin, nullptr, nullptr,
                  nullptr, b_out, g_lg);
    }
    gridbar();
    if (bid >= 32 && bid < 40) {
        int b = (bid - 32) * 8 + wid;
        lsm_row(b, out + (size_t)b * TSTEPS * VV + (size_t)(TSTEPS - 1) * VV);
    }
}

extern "C" void kernel_launch(void* const* d_in, const int* in_sizes, int n_in,
                              void* d_out, int out_size) {
    const float* enc    = (const float*)d_in[0];
    const float* W_emb  = (const float*)d_in[1];
    const float* W_comb = (const float*)d_in[2];
    const float* b_comb = (const float*)d_in[3];
    const float* W_ih   = (const float*)d_in[4];
    const float* W_hh   = (const float*)d_in[5];
    const float* b_ih   = (const float*)d_in[6];
    const float* b_hh   = (const float*)d_in[7];
    const float* W_out  = (const float*)d_in[8];
    const float* b_out  = (const float*)d_in[9];
    const float* w_vat  = (const float*)d_in[10];
    const float* b_vat  = (const float*)d_in[11];
    const int*   tgt    = (const int*)d_in[12];
    float* out = (float*)d_out;

    bahdanau_kernel<<<NB, NTH>>>(enc, W_emb, W_comb, b_comb, W_ih, W_hh,
                                 b_ih, b_hh, W_out, b_out, w_vat, b_vat,
                                 tgt, out);
}

// round 6
// speedup vs baseline: 1.3983x; 1.3983x over previous
#include <cuda_runtime.h>
#include <math_constants.h>
#include <cstdint>

#define SS      128
#define BB      64
#define HH      512
#define VV      100
#define TSTEPS  31
#define NTH     256
#define NB      296     // 2 CTAs/SM x 148 SMs, single wave

// dynamic smem layout (floats):
//   [0      .. 8192)   Wlo  : primary W tile  [k=128][j=64], k-major
//   [8192   .. 16384)  Whi  : secondary W tile (gi / comb-ctx)
//   [16384  .. 18560)  Ash  : A stage [32][68]   (union: attention h/w/sc)
//   [18560  .. 18624)  syms : int[64]
#define SM_WLO   0
#define SM_WHI   8192
#define SM_STAGE 16384
#define SM_SYMS  (16384 + 2176)
#define SMEM_FLOATS (16384 + 2176 + 64)
#define SMEM_BYTES (SMEM_FLOATS * 4)

// ---------------- persistent scratch ----------------
__device__ float g_hT[2][HH * BB];       // hidden transposed [h][b]
__device__ float g_ctxT[HH * BB];        // context transposed
__device__ float g_ghp[4][3 * HH * BB];  // gh K-quarter partials [j][b]
__device__ float g_gip[4][3 * HH * BB];  // gi K-quarter partials [j][b]
__device__ float g_cp[8][HH * BB];       // comb partials: q=0..3 emb, 4..7 ctx
__device__ float g_lgp[4][VV * BB];      // logit K-quarter partials [v][b]
__device__ unsigned g_barcnt = 0;
__device__ unsigned g_bargen = 0;

__device__ __forceinline__ float warp_sum(float v) {
#pragma unroll
    for (int o = 16; o; o >>= 1) v += __shfl_xor_sync(0xffffffffu, v, o);
    return v;
}
__device__ __forceinline__ float warp_max(float v) {
#pragma unroll
    for (int o = 16; o; o >>= 1) v = fmaxf(v, __shfl_xor_sync(0xffffffffu, v, o));
    return v;
}
__device__ __forceinline__ float fast_tanh(float x) {
    float r;
    asm("tanh.approx.f32 %0, %1;" : "=f"(r) : "f"(x));
    return r;
}

__device__ __forceinline__ void gridbar() {
    __syncthreads();
    if (threadIdx.x == 0) {
        __threadfence();
        unsigned gen = *((volatile unsigned*)&g_bargen);
        unsigned old = atomicAdd(&g_barcnt, 1u);
        if (old == NB - 1) {
            atomicExch(&g_barcnt, 0u);
            atomicExch(&g_bargen, gen + 1u);
        } else {
            while (*((volatile unsigned*)&g_bargen) == gen) { __nanosleep(32); }
        }
        __threadfence();
    }
    __syncthreads();
}

// preload one 64-row x 128-col W tile into smem, k-major [k][64]
__device__ void preload_w(float* Wdst, const float* __restrict__ Wg, int ldw,
                          int row0, int rowlim, int col0)
{
    for (int f = threadIdx.x; f < 2048; f += NTH) {   // float4 units along k
        int j = f >> 5;              // 0..63
        int k4 = (f & 31) * 4;       // 0..124
        int row = row0 + j;
        if (row >= rowlim) row = rowlim - 1;
        float4 w = *(const float4*)(Wg + (size_t)row * ldw + col0 + k4);
        Wdst[(k4 + 0) * 64 + j] = w.x;
        Wdst[(k4 + 1) * 64 + j] = w.y;
        Wdst[(k4 + 2) * 64 + j] = w.z;
        Wdst[(k4 + 3) * 64 + j] = w.w;
    }
}

// ---------------------------------------------------------------------------
// GEMM job with resident W: C[j0..j0+63][0..63] = Wres[k][j] * A[k][b],
// K = 128 (one quarter). Outer-product: thread (tx,ty) owns rows j0+tx*4..+3,
// cols ty*4..+3.
// mode 0: A0 = transposed activation (pre-offset by quarter), ldcg
// mode 1: A[k][b] = W_emb[syms[b]][c0+k]   (A0 = W_emb, c0 = quarter col)
// mode 2: A[k][b] = relu( sum_{q=0..7} g_cp[q][(kq*128+k)*64+b] + b_comb[..] )
// ---------------------------------------------------------------------------
__device__ void gemm64(float* smf, const float* Wres,
                       int j0, int rowlim, int mode,
                       const float* __restrict__ A0, int c0, int kq,
                       const int* __restrict__ tgt_t,
                       const float* __restrict__ b_comb,
                       float* __restrict__ Cout)
{
    const int tid = threadIdx.x;
    const int tx = tid & 15, ty = tid >> 4;
    float* Ash = smf + SM_STAGE;          // [32][68]
    int* syms = (int*)(smf + SM_SYMS);

    float acc[4][4];
#pragma unroll
    for (int r = 0; r < 4; r++)
#pragma unroll
        for (int c = 0; c < 4; c++) acc[r][c] = 0.f;

    if (mode == 1) {
        if (tid < BB) syms[tid] = tgt_t[tid];
        __syncthreads();
    }

#pragma unroll 1
    for (int kc = 0; kc < 128; kc += 32) {
        // ---- stage A tile [32][64] ----
        if (mode == 0) {
            int e = tid * 8, k = e >> 6, b = e & 63;
            float4 u0 = __ldcg((const float4*)(A0 + kc * 64 + e));
            float4 u1 = __ldcg((const float4*)(A0 + kc * 64 + e + 4));
            *(float4*)&Ash[k * 68 + b]     = u0;
            *(float4*)&Ash[k * 68 + b + 4] = u1;
        } else if (mode == 1) {
            int b = tid >> 2, kg = (tid & 3) * 8;
            const float* src = A0 + (size_t)syms[b] * HH + c0 + kc + kg;
            float4 v0 = *(const float4*)src;
            float4 v1 = *(const float4*)(src + 4);
            Ash[(kg + 0) * 68 + b] = v0.x; Ash[(kg + 1) * 68 + b] = v0.y;
            Ash[(kg + 2) * 68 + b] = v0.z; Ash[(kg + 3) * 68 + b] = v0.w;
            Ash[(kg + 4) * 68 + b] = v1.x; Ash[(kg + 5) * 68 + b] = v1.y;
            Ash[(kg + 6) * 68 + b] = v1.z; Ash[(kg + 7) * 68 + b] = v1.w;
        } else {
            int e = tid * 8, k = e >> 6, b = e & 63;
            size_t gx = (size_t)(kq * 128 + kc + k) * 64 + b;
            float bc = b_comb[kq * 128 + kc + k];
            float s0 = bc, s1 = bc, s2 = bc, s3 = bc;
            float s4 = bc, s5 = bc, s6 = bc, s7 = bc;
#pragma unroll
            for (int q = 0; q < 8; q++) {
                float4 u0 = __ldcg((const float4*)(g_cp[q] + gx));
                float4 u1 = __ldcg((const float4*)(g_cp[q] + gx + 4));
                s0 += u0.x; s1 += u0.y; s2 += u0.z; s3 += u0.w;
                s4 += u1.x; s5 += u1.y; s6 += u1.z; s7 += u1.w;
            }
            float* dst = &Ash[k * 68 + b];
            dst[0] = fmaxf(s0, 0.f); dst[1] = fmaxf(s1, 0.f);
            dst[2] = fmaxf(s2, 0.f); dst[3] = fmaxf(s3, 0.f);
            dst[4] = fmaxf(s4, 0.f); dst[5] = fmaxf(s5, 0.f);
            dst[6] = fmaxf(s6, 0.f); dst[7] = fmaxf(s7, 0.f);
        }
        __syncthreads();
#pragma unroll
        for (int k = 0; k < 32; k++) {
            float4 w4 = *(const float4*)&Wres[(kc + k) * 64 + tx * 4];
            float4 a4 = *(const float4*)&Ash[k * 68 + ty * 4];
            acc[0][0] = fmaf(w4.x, a4.x, acc[0][0]);
            acc[0][1] = fmaf(w4.x, a4.y, acc[0][1]);
            acc[0][2] = fmaf(w4.x, a4.z, acc[0][2]);
            acc[0][3] = fmaf(w4.x, a4.w, acc[0][3]);
            acc[1][0] = fmaf(w4.y, a4.x, acc[1][0]);
            acc[1][1] = fmaf(w4.y, a4.y, acc[1][1]);
            acc[1][2] = fmaf(w4.y, a4.z, acc[1][2]);
            acc[1][3] = fmaf(w4.y, a4.w, acc[1][3]);
            acc[2][0] = fmaf(w4.z, a4.x, acc[2][0]);
            acc[2][1] = fmaf(w4.z, a4.y, acc[2][1]);
            acc[2][2] = fmaf(w4.z, a4.z, acc[2][2]);
            acc[2][3] = fmaf(w4.z, a4.w, acc[2][3]);
            acc[3][0] = fmaf(w4.w, a4.x, acc[3][0]);
            acc[3][1] = fmaf(w4.w, a4.y, acc[3][1]);
            acc[3][2] = fmaf(w4.w, a4.z, acc[3][2]);
            acc[3][3] = fmaf(w4.w, a4.w, acc[3][3]);
        }
        __syncthreads();
    }
#pragma unroll
    for (int r = 0; r < 4; r++) {
        int row = j0 + tx * 4 + r;
        if (row < rowlim) {
            *(float4*)(Cout + (size_t)row * BB + ty * 4) =
                make_float4(acc[r][0], acc[r][1], acc[r][2], acc[r][3]);
        }
    }
}

// ---------------------------------------------------------------------------
// Bahdanau attention for batch element b (block-collective). Proven (R3).
// ---------------------------------------------------------------------------
__device__ void attention_block(float* smf, int b,
                                const float* __restrict__ enc,
                                const float* __restrict__ w_vat,
                                const float* __restrict__ b_vat,
                                const float* __restrict__ hT,
                                float* __restrict__ ctxT)
{
    float* sh_h = smf + SM_STAGE;
    float* sh_w = sh_h + HH;
    float* sh_sc = sh_w + HH;
    const int tid = threadIdx.x, wid = tid >> 5, lane = tid & 31;
    for (int i = tid; i < HH; i += NTH) {
        sh_h[i] = __ldcg(&hT[i * BB + b]);
        sh_w[i] = w_vat[i];
    }
    __syncthreads();
    const float bv = b_vat[0];
    const float4* hp = (const float4*)sh_h;
    const float4* wp = (const float4*)sh_w;
    for (int s = wid; s < SS; s += NTH / 32) {
        const float4* ep = (const float4*)(enc + ((size_t)s * BB + b) * HH);
        float acc = 0.f;
#pragma unroll
        for (int c = 0; c < 4; c++) {
            int k = lane + 32 * c;
            float4 e = ep[k], h4 = hp[k], w4 = wp[k];
            acc += fast_tanh(e.x + h4.x) * w4.x;
            acc += fast_tanh(e.y + h4.y) * w4.y;
            acc += fast_tanh(e.z + h4.z) * w4.z;
            acc += fast_tanh(e.w + h4.w) * w4.w;
        }
        acc = warp_sum(acc);
        if (lane == 0) sh_sc[s] = acc + bv;
    }
    __syncthreads();
    if (wid == 0) {
        float v0 = sh_sc[lane],      v1 = sh_sc[lane + 32];
        float v2 = sh_sc[lane + 64], v3 = sh_sc[lane + 96];
        float m = warp_max(fmaxf(fmaxf(v0, v1), fmaxf(v2, v3)));
        float e0 = expf(v0 - m), e1 = expf(v1 - m);
        float e2 = expf(v2 - m), e3 = expf(v3 - m);
        float inv = 1.f / warp_sum(e0 + e1 + e2 + e3);
        sh_sc[lane]      = e0 * inv; sh_sc[lane + 32] = e1 * inv;
        sh_sc[lane + 64] = e2 * inv; sh_sc[lane + 96] = e3 * inv;
    }
    __syncthreads();
    {
        const int h0 = tid * 2;
        const float* base = enc + (size_t)b * HH + h0;
        float a0 = 0.f, a1 = 0.f;
#pragma unroll 4
        for (int s = 0; s < SS; s++) {
            float wv = sh_sc[s];
            float2 e = *(const float2*)(base + (size_t)s * (BB * HH));
            a0 = fmaf(wv, e.x, a0);
            a1 = fmaf(wv, e.y, a1);
        }
        ctxT[h0 * BB + b]       = a0;
        ctxT[(h0 + 1) * BB + b] = a1;
    }
    __syncthreads();
}

// log-softmax for batch column b (one warp), summing 4 logit partials.
__device__ void lsm_row(int b, const float* __restrict__ b_out,
                        float* __restrict__ outp)
{
    const int lane = threadIdx.x & 31;
    float v0 = b_out[lane], v1 = b_out[lane + 32], v2 = b_out[lane + 64];
    bool ok3 = lane < (VV - 96);
    float v3 = ok3 ? b_out[lane + 96] : 0.f;
#pragma unroll
    for (int q = 0; q < 4; q++) {
        v0 += __ldcg(&g_lgp[q][lane * BB + b]);
        v1 += __ldcg(&g_lgp[q][(lane + 32) * BB + b]);
        v2 += __ldcg(&g_lgp[q][(lane + 64) * BB + b]);
        if (ok3) v3 += __ldcg(&g_lgp[q][(lane + 96) * BB + b]);
    }
    if (!ok3) v3 = -CUDART_INF_F;
    float m = warp_max(fmaxf(fmaxf(v0, v1), fmaxf(v2, v3)));
    float s = expf(v0 - m) + expf(v1 - m) + expf(v2 - m) + (ok3 ? expf(v3 - m) : 0.f);
    s = warp_sum(s);
    float lse = m + logf(s);
    outp[lane]      = v0 - lse;
    outp[lane + 32] = v1 - lse;
    outp[lane + 64] = v2 - lse;
    if (ok3) outp[lane + 96] = v3 - lse;
}

__global__ void __launch_bounds__(NTH, 2)
bahdanau_kernel(
    const float* __restrict__ enc,    const float* __restrict__ W_emb,
    const float* __restrict__ W_comb, const float* __restrict__ b_comb,
    const float* __restrict__ W_ih,   const float* __restrict__ W_hh,
    const float* __restrict__ b_ih,   const float* __restrict__ b_hh,
    const float* __restrict__ W_out,  const float* __restrict__ b_out,
    const float* __restrict__ w_vat,  const float* __restrict__ b_vat,
    const int* __restrict__ tgt, float* __restrict__ out)
{
    extern __shared__ float smf[];
    const int bid = blockIdx.x;
    const int tid = threadIdx.x;
    const int wid = tid >> 5;

    // ---- one-time W preload (fixed job identity per CTA) ----
    if (bid >= 64 && bid < 160) {
        int g = bid - 64, mt = g >> 2, kq = g & 3;
        preload_w(smf + SM_WLO, W_hh, HH, mt * 64, 3 * HH, kq * 128);
        preload_w(smf + SM_WHI, W_ih, HH, mt * 64, 3 * HH, kq * 128);
    } else if (bid >= 160 && bid < 168) {
        int g = bid - 160, mt = g >> 2, kq = g & 3;
        preload_w(smf + SM_WLO, W_out, HH, mt * 64, VV, kq * 128);
    } else if (bid >= 168 && bid < 200) {
        int g = bid - 168, mt = g >> 2, kq = g & 3;
        preload_w(smf + SM_WLO, W_comb, 2 * HH, mt * 64, HH, kq * 128);
        preload_w(smf + SM_WHI, W_comb, 2 * HH, mt * 64, HH, HH + kq * 128);
    }
    // zero initial hidden state
    for (int i = bid * NTH + tid; i < HH * BB; i += NB * NTH) g_hT[0][i] = 0.f;
    gridbar();

    for (int t = 0; t < TSTEPS; t++) {
        const float* hcur = g_hT[t & 1];
        float* hnext = g_hT[(t + 1) & 1];

        // === PA: attention(0-63) | gh(64-159) | logits prev(160-167)
        //         | comb-emb(168-199) ===
        if (bid < BB) {
            attention_block(smf, bid, enc, w_vat, b_vat, hcur, g_ctxT);
        } else if (bid < 160) {
            int g = bid - 64, mt = g >> 2, kq = g & 3;
            gemm64(smf, smf + SM_WLO, mt * 64, 3 * HH, 0,
                   hcur + kq * 128 * BB, 0, kq, nullptr, nullptr, g_ghp[kq]);
        } else if (bid < 168) {
            if (t >= 1) {
                int g = bid - 160, mt = g >> 2, kq = g & 3;
                gemm64(smf, smf + SM_WLO, mt * 64, VV, 0,
                       hcur + kq * 128 * BB, 0, kq, nullptr, nullptr, g_lgp[kq]);
            }
        } else if (bid < 200) {
            int g = bid - 168, mt = g >> 2, kq = g & 3;
            gemm64(smf, smf + SM_WLO, mt * 64, HH, 1,
                   W_emb, kq * 128, kq, tgt + t * BB, nullptr, g_cp[kq]);
        }
        gridbar();

        // === PB: comb-ctx(168-199) | lsm prev(0-7) ===
        if (bid >= 168 && bid < 200) {
            int g = bid - 168, mt = g >> 2, kq = g & 3;
            gemm64(smf, smf + SM_WHI, mt * 64, HH, 0,
                   g_ctxT + kq * 128 * BB, 0, kq, nullptr, nullptr, g_cp[4 + kq]);
        } else if (bid < 8) {
            if (t >= 1) {
                int b = bid * 8 + wid;
                lsm_row(b, b_out, out + (size_t)b * TSTEPS * VV + (size_t)(t - 1) * VV);
            }
        }
        gridbar();

        // === PC: gi(64-159), A materialized from 8 comb partials ===
        if (bid >= 64 && bid < 160) {
            int g = bid - 64, mt = g >> 2, kq = g & 3;
            gemm64(smf, smf + SM_WHI, mt * 64, 3 * HH, 2,
                   nullptr, 0, kq, nullptr, b_comb, g_gip[kq]);
        }
        gridbar();

        // === PD: GRU gates elementwise (sum 4+4 partials) ===
        {
            int e = bid * NTH + tid;
            if (e < HH * BB) {
                int i = e >> 6, b = e & 63;
                size_t ir = (size_t)i * BB + b;
                size_t iz = (size_t)(i + HH) * BB + b;
                size_t in_ = (size_t)(i + 2 * HH) * BB + b;
                float gir = b_ih[i], giz = b_ih[i + HH], gin = b_ih[i + 2 * HH];
                float ghr = b_hh[i], ghz = b_hh[i + HH], ghn = b_hh[i + 2 * HH];
#pragma unroll
                for (int q = 0; q < 4; q++) {
                    gir += __ldcg(&g_gip[q][ir]);
                    giz += __ldcg(&g_gip[q][iz]);
                    gin += __ldcg(&g_gip[q][in_]);
                    ghr += __ldcg(&g_ghp[q][ir]);
                    ghz += __ldcg(&g_ghp[q][iz]);
                    ghn += __ldcg(&g_ghp[q][in_]);
                }
                float ho = __ldcg(&hcur[ir]);
                float r = 1.f / (1.f + expf(-(gir + ghr)));
                float z = 1.f / (1.f + expf(-(giz + ghz)));
                float n = tanhf(gin + r * ghn);
                hnext[ir] = (1.f - z) * n + z * ho;
            }
        }
        gridbar();
    }

    // ===== final logits (slot TSTEPS-1) =====
    const float* hfin = g_hT[TSTEPS & 1];
    if (bid >= 160 && bid < 168) {
        int g = bid - 160, mt = g >> 2, kq = g & 3;
        gemm64(smf, smf + SM_WLO, mt * 64, VV, 0,
               hfin + kq * 128 * BB, 0, kq, nullptr, nullptr, g_lgp[kq]);
    }
    gridbar();
    if (bid < 8) {
        int b = bid * 8 + wid;
        lsm_row(b, b_out, out + (size_t)b * TSTEPS * VV + (size_t)(TSTEPS - 1) * VV);
    }
}

extern "C" void kernel_launch(void* const* d_in, const int* in_sizes, int n_in,
                              void* d_out, int out_size) {
    const float* enc    = (const float*)d_in[0];
    const float* W_emb  = (const float*)d_in[1];
    const float* W_comb = (const float*)d_in[2];
    const float* b_comb = (const float*)d_in[3];
    const float* W_ih   = (const float*)d_in[4];
    const float* W_hh   = (const float*)d_in[5];
    const float* b_ih   = (const float*)d_in[6];
    const float* b_hh   = (const float*)d_in[7];
    const float* W_out  = (const float*)d_in[8];
    const float* b_out  = (const float*)d_in[9];
    const float* w_vat  = (const float*)d_in[10];
    const float* b_vat  = (const float*)d_in[11];
    const int*   tgt    = (const int*)d_in[12];
    float* out = (float*)d_out;

    cudaFuncSetAttribute(bahdanau_kernel,
                         cudaFuncAttributeMaxDynamicSharedMemorySize, SMEM_BYTES);
    bahdanau_kernel<<<NB, NTH, SMEM_BYTES>>>(enc, W_emb, W_comb, b_comb,
                                             W_ih, W_hh, b_ih, b_hh,
                                             W_out, b_out, w_vat, b_vat,
                                             tgt, out);
}